// round 2
// baseline (speedup 1.0000x reference)
#include <cuda_runtime.h>
#include <math.h>

#define NROWS 100352   // B * D * H * W tokens (also total window rows: 1024 windows * 98)
#define CDIM  192

// ---------------- scratch (device globals; no allocations allowed) ----------
__device__ float g_xw[(size_t)NROWS * CDIM];        // LN'd, rolled, window-partitioned
__device__ float g_qkv[(size_t)3 * NROWS * CDIM];   // [3][win][head][98][32]
__device__ float g_attnout[(size_t)NROWS * CDIM];   // window-row-major, col = head*32+d
__device__ float g_projout[(size_t)NROWS * CDIM];   // token-major (after reverse+roll)

// Map window-row index -> original token index. Forward gather (roll -S then
// partition) and inverse scatter (reverse then roll +S) use the SAME map.
__device__ __forceinline__ int row_to_token(int row) {
    int win = row / 98;
    int tok = row - win * 98;
    int b = win >> 8, wib = win & 255;
    int wd = wib >> 6, wh = (wib >> 3) & 7, wwi = wib & 7;
    int md = tok / 49; int r2 = tok - md * 49; int mh = r2 / 7; int mw = r2 - mh * 7;
    int d = (wd * 2 + md + 1) & 7;
    int h = wh * 7 + mh + 3; if (h >= 56) h -= 56;
    int w = wwi * 7 + mw + 3; if (w >= 56) w -= 56;
    return ((b * 8 + d) * 56 + h) * 56 + w;
}

// ---------------- LayerNorm + roll + window partition (warp per token) ------
__global__ void __launch_bounds__(256) ln_gather_k(const float* __restrict__ x,
        const float* __restrict__ gg, const float* __restrict__ bb) {
    int row = blockIdx.x * 8 + (threadIdx.x >> 5);
    int lane = threadIdx.x & 31;
    int t = row_to_token(row);
    const float* xp = x + (size_t)t * CDIM;
    float v[6]; float s = 0.f;
    #pragma unroll
    for (int j = 0; j < 6; j++) { v[j] = xp[lane + 32 * j]; s += v[j]; }
    #pragma unroll
    for (int o = 16; o > 0; o >>= 1) s += __shfl_xor_sync(0xffffffffu, s, o);
    float mu = s * (1.f / 192.f);
    float var = 0.f;
    #pragma unroll
    for (int j = 0; j < 6; j++) { float dd = v[j] - mu; var += dd * dd; }
    #pragma unroll
    for (int o = 16; o > 0; o >>= 1) var += __shfl_xor_sync(0xffffffffu, var, o);
    float r = rsqrtf(var * (1.f / 192.f) + 1e-5f);
    float* op = g_xw + (size_t)row * CDIM;
    #pragma unroll
    for (int j = 0; j < 6; j++) {
        int c = lane + 32 * j;
        op[c] = (v[j] - mu) * r * gg[c] + bb[c];
    }
}

// ---------------- tiled SGEMM: out(M x N) = A(M x 192) @ Bw(N x 192)^T ------
// 128x64 block tile, 8x4 micro tile, K-chunks of 8. Three epilogue modes:
//   MODE 0: QKV  (A = g_xw,      scatter to g_qkv head-major + bias)
//   MODE 1: proj (A = g_attnout, scatter rows to token order into g_projout + bias)
//   MODE 2: fc1  (A = g_projout, out = shortcut + gelu(acc + bias))
template<int MODE>
__global__ void __launch_bounds__(256) gemm_k(const float* __restrict__ Bw,
        const float* __restrict__ bias, const float* __restrict__ shortcut,
        float* __restrict__ Out) {
    __shared__ float As[8][128];
    __shared__ float Bs[8][64];
    const float* A = (MODE == 0) ? g_xw : (MODE == 1) ? g_attnout : g_projout;
    const int tid = threadIdx.x;
    const int m0 = blockIdx.y * 128, n0 = blockIdx.x * 64;
    const int tm = (tid >> 4) << 3;     // 0..120
    const int tn = (tid & 15) << 2;     // 0..60
    float acc[8][4];
    #pragma unroll
    for (int i = 0; i < 8; i++)
        #pragma unroll
        for (int j = 0; j < 4; j++) acc[i][j] = 0.f;

    const int ar = tid >> 1, ak = (tid & 1) << 2;
    const float* Ap = A + (size_t)(m0 + ar) * CDIM + ak;
    const float* Bp = Bw + (size_t)(n0 + ar) * CDIM + ak;  // only tid<128 uses

    for (int kc = 0; kc < 24; kc++) {
        float4 av = *(const float4*)(Ap + kc * 8);
        float4 bv = make_float4(0.f, 0.f, 0.f, 0.f);
        if (tid < 128) bv = *(const float4*)(Bp + kc * 8);
        __syncthreads();
        As[ak + 0][ar] = av.x; As[ak + 1][ar] = av.y;
        As[ak + 2][ar] = av.z; As[ak + 3][ar] = av.w;
        if (tid < 128) {
            Bs[ak + 0][ar] = bv.x; Bs[ak + 1][ar] = bv.y;
            Bs[ak + 2][ar] = bv.z; Bs[ak + 3][ar] = bv.w;
        }
        __syncthreads();
        #pragma unroll
        for (int kk = 0; kk < 8; kk++) {
            float4 a0 = *(const float4*)&As[kk][tm];
            float4 a1 = *(const float4*)&As[kk][tm + 4];
            float4 b  = *(const float4*)&Bs[kk][tn];
            float aa[8] = {a0.x, a0.y, a0.z, a0.w, a1.x, a1.y, a1.z, a1.w};
            float bb4[4] = {b.x, b.y, b.z, b.w};
            #pragma unroll
            for (int i = 0; i < 8; i++)
                #pragma unroll
                for (int j = 0; j < 4; j++) acc[i][j] += aa[i] * bb4[j];
        }
    }

    if (MODE == 0) {
        int n = n0 + tn;
        int sI = n / 192, rI = n - sI * 192;
        int hI = rI >> 5, dI = rI & 31;
        #pragma unroll
        for (int i = 0; i < 8; i++) {
            int m = m0 + tm + i;
            int win = m / 98, tok = m - win * 98;
            float* o = g_qkv + (((size_t)sI * 1024 + win) * 6 + hI) * 3136 + tok * 32 + dI;
            #pragma unroll
            for (int j = 0; j < 4; j++) o[j] = acc[i][j] + bias[n + j];
        }
    } else if (MODE == 1) {
        #pragma unroll
        for (int i = 0; i < 8; i++) {
            int m = m0 + tm + i;
            int t = row_to_token(m);
            float* o = g_projout + (size_t)t * CDIM + n0 + tn;
            #pragma unroll
            for (int j = 0; j < 4; j++) o[j] = acc[i][j] + bias[n0 + tn + j];
        }
    } else {
        #pragma unroll
        for (int i = 0; i < 8; i++) {
            int m = m0 + tm + i;
            #pragma unroll
            for (int j = 0; j < 4; j++) {
                int n = n0 + tn + j;
                float v = acc[i][j] + bias[n];
                float g = 0.5f * v * (1.f + erff(v * 0.70710678118654752f));
                Out[(size_t)m * CDIM + n] = shortcut[(size_t)m * CDIM + n] + g;
            }
        }
    }
}

// ---------------- attention: one block per (window, head) -------------------
// smem: Q/K/V padded rows of 33 floats (conflict-free), S padded rows of 100.
// Ss base offset padded to 9704 floats so it is 16-byte aligned for float4.
__global__ void __launch_bounds__(128) attn_k(const float* __restrict__ amask,
                                              const float* __restrict__ relb) {
    extern __shared__ float sm[];
    float* Qs = sm;                 // 98*33 = 3234
    float* Ks = Qs + 3234;
    float* Vs = Ks + 3234;
    float* Ss = sm + 9704;          // 16B-aligned base; 98 rows * 100 stride
    const int win = blockIdx.x / 6, head = blockIdx.x % 6;
    const int tid = threadIdx.x, warp = tid >> 5, lane = tid & 31;
    const size_t base = ((size_t)win * 6 + head) * 3136;
    const float* qg = g_qkv + base;
    const float* kg = g_qkv + (size_t)19267584 + base;
    const float* vg = g_qkv + (size_t)2 * 19267584 + base;
    for (int i = tid; i < 3136; i += 128) {
        int r = i >> 5, d = i & 31;
        Qs[r * 33 + d] = qg[i];
        Ks[r * 33 + d] = kg[i];
        Vs[r * 33 + d] = vg[i];
    }
    __syncthreads();

    // ---- scores S = scale * Q K^T + bias + mask ----
    const float* mw = amask + (size_t)(win & 255) * 9604;
    for (int nb = warp * 4; nb < 98; nb += 16) {
        float acc[4][4];
        #pragma unroll
        for (int r = 0; r < 4; r++)
            #pragma unroll
            for (int j = 0; j < 4; j++) acc[r][j] = 0.f;
        #pragma unroll 4
        for (int d = 0; d < 32; d++) {
            float kv0 = Ks[lane * 33 + d];
            float kv1 = Ks[(lane + 32) * 33 + d];
            float kv2 = Ks[(lane + 64) * 33 + d];
            float kv3 = (lane < 2) ? Ks[(lane + 96) * 33 + d] : 0.f;
            #pragma unroll
            for (int r = 0; r < 4; r++) {
                int n = nb + r;
                float qv = (n < 98) ? Qs[n * 33 + d] : 0.f;
                acc[r][0] += qv * kv0;
                acc[r][1] += qv * kv1;
                acc[r][2] += qv * kv2;
                acc[r][3] += qv * kv3;
            }
        }
        #pragma unroll
        for (int r = 0; r < 4; r++) {
            int n = nb + r;
            if (n < 98) {
                int nd = n / 49, r2 = n % 49, nh = r2 / 7, nw = r2 % 7;
                #pragma unroll
                for (int j = 0; j < 4; j++) {
                    int m = lane + 32 * j;
                    if (m < 98) {
                        int md2 = m / 49, m2 = m % 49, mh2 = m2 / 7, mw2 = m2 % 7;
                        int ridx = (nd - md2 + 1) * 169 + (nh - mh2 + 6) * 13 + (nw - mw2 + 6);
                        Ss[n * 100 + m] = acc[r][j] * 0.17677669529663687f
                                        + relb[ridx * 6 + head] + mw[n * 98 + m];
                    }
                }
            }
        }
    }
    __syncthreads();

    // ---- row softmax (warp per row) ----
    for (int n = warp; n < 98; n += 4) {
        float v[4]; float mx = -1e30f;
        #pragma unroll
        for (int j = 0; j < 4; j++) {
            int m = lane + 32 * j;
            v[j] = (m < 98) ? Ss[n * 100 + m] : -1e30f;
            mx = fmaxf(mx, v[j]);
        }
        #pragma unroll
        for (int o = 16; o > 0; o >>= 1) mx = fmaxf(mx, __shfl_xor_sync(0xffffffffu, mx, o));
        float s = 0.f;
        #pragma unroll
        for (int j = 0; j < 4; j++) {
            int m = lane + 32 * j;
            v[j] = (m < 98) ? __expf(v[j] - mx) : 0.f;
            s += v[j];
        }
        #pragma unroll
        for (int o = 16; o > 0; o >>= 1) s += __shfl_xor_sync(0xffffffffu, s, o);
        float inv = 1.f / s;
        #pragma unroll
        for (int j = 0; j < 4; j++) {
            int m = lane + 32 * j;
            if (m < 98) Ss[n * 100 + m] = v[j] * inv;
        }
    }
    __syncthreads();

    // ---- O = S @ V  (8 rows per warp per pass, d = lane) ----
    const int d = lane;
    for (int nb = warp * 8; nb < 98; nb += 32) {
        float acc[8];
        #pragma unroll
        for (int r = 0; r < 8; r++) acc[r] = 0.f;
        for (int mq = 0; mq < 24; mq++) {
            float vv0 = Vs[(mq * 4 + 0) * 33 + d];
            float vv1 = Vs[(mq * 4 + 1) * 33 + d];
            float vv2 = Vs[(mq * 4 + 2) * 33 + d];
            float vv3 = Vs[(mq * 4 + 3) * 33 + d];
            #pragma unroll
            for (int r = 0; r < 8; r++) {
                int n = nb + r;
                if (n < 98) {
                    float4 sv = *(const float4*)&Ss[n * 100 + mq * 4];
                    acc[r] += sv.x * vv0 + sv.y * vv1 + sv.z * vv2 + sv.w * vv3;
                }
            }
        }
        float v96 = Vs[96 * 33 + d], v97 = Vs[97 * 33 + d];
        #pragma unroll
        for (int r = 0; r < 8; r++) {
            int n = nb + r;
            if (n < 98) {
                acc[r] += Ss[n * 100 + 96] * v96 + Ss[n * 100 + 97] * v97;
                g_attnout[(size_t)(win * 98 + n) * CDIM + head * 32 + d] = acc[r];
            }
        }
    }
}

// ---------------- launch ----------------------------------------------------
extern "C" void kernel_launch(void* const* d_in, const int* in_sizes, int n_in,
                              void* d_out, int out_size) {
    const float* x     = (const float*)d_in[0];
    const float* amask = (const float*)d_in[1];
    const float* n1g   = (const float*)d_in[2];
    const float* n1b   = (const float*)d_in[3];
    const float* qkvw  = (const float*)d_in[4];
    const float* qkvb  = (const float*)d_in[5];
    const float* relb  = (const float*)d_in[6];
    const float* projw = (const float*)d_in[7];
    const float* projb = (const float*)d_in[8];
    const float* fc1w  = (const float*)d_in[9];
    const float* fc1b  = (const float*)d_in[10];
    float* out = (float*)d_out;
    (void)in_sizes; (void)n_in; (void)out_size;

    cudaFuncSetAttribute(attn_k, cudaFuncAttributeMaxDynamicSharedMemorySize, 80000);

    // 1) LN + roll + window partition
    ln_gather_k<<<12544, 256>>>(x, n1g, n1b);
    // 2) QKV GEMM (M=100352, N=576, K=192)
    gemm_k<0><<<dim3(9, 784), 256>>>(qkvw, qkvb, nullptr, nullptr);
    // 3) windowed attention, 1024 windows x 6 heads
    attn_k<<<6144, 128, 78016>>>(amask, relb);
    // 4) proj GEMM + window reverse + roll-back scatter (N=192)
    gemm_k<1><<<dim3(3, 784), 256>>>(projw, projb, nullptr, nullptr);
    // 5) fc1 GEMM + exact GELU + shortcut add (N=192)
    gemm_k<2><<<dim3(3, 784), 256>>>(fc1w, fc1b, x, out);
}

// round 4
// speedup vs baseline: 5.1303x; 5.1303x over previous
#include <cuda_runtime.h>
#include <cuda_bf16.h>
#include <math.h>

#define NROWS 100352   // B*D*H*W tokens == total window rows (1024 windows * 98)
#define CDIM  192
#define SCALE 0.17677669529663687f

typedef __nv_bfloat16 bf16;

// ---------------- scratch (device globals) ----------------------------------
__device__ bf16 g_xw[(size_t)NROWS * CDIM];        // LN'd+rolled+partitioned (window-row major)
__device__ bf16 g_qkv[(size_t)3 * NROWS * CDIM];   // [3][win][head][98][32]
__device__ bf16 g_attnout[(size_t)NROWS * CDIM];   // window-row major, col = head*32+d
__device__ bf16 g_projout[(size_t)NROWS * CDIM];   // token major
__device__ bf16 g_wq[576 * 192];
__device__ bf16 g_wp[192 * 192];
__device__ bf16 g_wf[192 * 192];
__device__ float g_bias6[6 * 98 * 98];             // rel_bias expanded per head

// ---------------- helpers ---------------------------------------------------
__device__ __forceinline__ int row_to_token(int row) {
    int win = row / 98;
    int tok = row - win * 98;
    int b = win >> 8, wib = win & 255;
    int wd = wib >> 6, wh = (wib >> 3) & 7, wwi = wib & 7;
    int md = tok / 49; int r2 = tok - md * 49; int mh = r2 / 7; int mw = r2 - mh * 7;
    int d = (wd * 2 + md + 1) & 7;
    int h = wh * 7 + mh + 3; if (h >= 56) h -= 56;
    int w = wwi * 7 + mw + 3; if (w >= 56) w -= 56;
    return ((b * 8 + d) * 56 + h) * 56 + w;
}

__device__ __forceinline__ unsigned smem_u32(const void* p) {
    return (unsigned)__cvta_generic_to_shared(p);
}
__device__ __forceinline__ void ldsm_x4(unsigned r[4], unsigned addr) {
    asm volatile("ldmatrix.sync.aligned.m8n8.x4.shared.b16 {%0,%1,%2,%3}, [%4];"
                 : "=r"(r[0]), "=r"(r[1]), "=r"(r[2]), "=r"(r[3]) : "r"(addr));
}
__device__ __forceinline__ void ldsm_x4_t(unsigned r[4], unsigned addr) {
    asm volatile("ldmatrix.sync.aligned.m8n8.x4.trans.shared.b16 {%0,%1,%2,%3}, [%4];"
                 : "=r"(r[0]), "=r"(r[1]), "=r"(r[2]), "=r"(r[3]) : "r"(addr));
}
__device__ __forceinline__ void mma16816(float c[4], const unsigned a[4], unsigned b0, unsigned b1) {
    asm volatile("mma.sync.aligned.m16n8k16.row.col.f32.bf16.bf16.f32 "
                 "{%0,%1,%2,%3},{%4,%5,%6,%7},{%8,%9},{%0,%1,%2,%3};"
                 : "+f"(c[0]), "+f"(c[1]), "+f"(c[2]), "+f"(c[3])
                 : "r"(a[0]), "r"(a[1]), "r"(a[2]), "r"(a[3]), "r"(b0), "r"(b1));
}
__device__ __forceinline__ unsigned pack2(float lo, float hi) {
    __nv_bfloat162 h = __floats2bfloat162_rn(lo, hi);
    return *reinterpret_cast<unsigned*>(&h);
}

// ---------------- tiny prep kernels -----------------------------------------
__global__ void convert_w_k(const float* __restrict__ qw, const float* __restrict__ pw,
                            const float* __restrict__ fw) {
    int i = blockIdx.x * 256 + threadIdx.x;          // 184320 total
    if (i < 110592)       g_wq[i] = __float2bfloat16(qw[i]);
    else if (i < 147456)  g_wp[i - 110592] = __float2bfloat16(pw[i - 110592]);
    else                  g_wf[i - 147456] = __float2bfloat16(fw[i - 147456]);
}

__global__ void bias_expand_k(const float* __restrict__ relb) {
    int i = blockIdx.x * 256 + threadIdx.x;
    if (i >= 9604) return;
    int q = i / 98, j = i - q * 98;
    int nd = q / 49, r2 = q % 49, nh = r2 / 7, nw = r2 % 7;
    int md = j / 49, m2 = j % 49, mh = m2 / 7, mw = m2 % 7;
    int ridx = (nd - md + 1) * 169 + (nh - mh + 6) * 13 + (nw - mw + 6);
    #pragma unroll
    for (int h = 0; h < 6; h++)
        g_bias6[h * 9604 + i] = relb[ridx * 6 + h];
}

// ---------------- LayerNorm + roll + window partition ------------------------
__global__ void __launch_bounds__(256) ln_gather_k(const float* __restrict__ x,
        const float* __restrict__ gg, const float* __restrict__ bb) {
    int row = blockIdx.x * 8 + (threadIdx.x >> 5);
    int lane = threadIdx.x & 31;
    int t = row_to_token(row);
    const float* xp = x + (size_t)t * CDIM;
    float v[6]; float s = 0.f;
    #pragma unroll
    for (int j = 0; j < 6; j++) { v[j] = xp[lane + 32 * j]; s += v[j]; }
    #pragma unroll
    for (int o = 16; o > 0; o >>= 1) s += __shfl_xor_sync(0xffffffffu, s, o);
    float mu = s * (1.f / 192.f);
    float var = 0.f;
    #pragma unroll
    for (int j = 0; j < 6; j++) { float dd = v[j] - mu; var += dd * dd; }
    #pragma unroll
    for (int o = 16; o > 0; o >>= 1) var += __shfl_xor_sync(0xffffffffu, var, o);
    float r = rsqrtf(var * (1.f / 192.f) + 1e-5f);
    bf16* op = g_xw + (size_t)row * CDIM;
    #pragma unroll
    for (int j = 0; j < 6; j++) {
        int c = lane + 32 * j;
        op[c] = __float2bfloat16((v[j] - mu) * r * gg[c] + bb[c]);
    }
}

// ---------------- bf16 tensor-core GEMM: C(MxN) = A(Mx192) @ W(Nx192)^T ------
// CTA 128x64, 8 warps (32x32 each), K=192 in smem (stride 200 bf16).
// MODE 0: QKV -> g_qkv scatter (bf16). MODE 1: proj -> g_projout token scatter.
// MODE 2: fc1 -> out = shortcut + gelu(acc+bias) (fp32).
template<int MODE>
__global__ void __launch_bounds__(256) gemm_mma(const float* __restrict__ bias,
        const float* __restrict__ shortcut, float* __restrict__ Out) {
    extern __shared__ __align__(16) bf16 sm[];
    bf16* As = sm;                // 128 x 200
    bf16* Ws = sm + 128 * 200;    // 64 x 200
    const bf16* A = (MODE == 0) ? g_xw : (MODE == 1) ? g_attnout : g_projout;
    const bf16* W = (MODE == 0) ? g_wq : (MODE == 1) ? g_wp : g_wf;
    const int tid = threadIdx.x;
    const int m0 = blockIdx.y * 128, n0 = blockIdx.x * 64;

    #pragma unroll
    for (int i = 0; i < 12; i++) {
        int u = tid + i * 256;                    // < 3072
        int row = u / 24, c8 = u - row * 24;
        *(uint4*)&As[row * 200 + c8 * 8] = *(const uint4*)&A[(size_t)(m0 + row) * 192 + c8 * 8];
    }
    #pragma unroll
    for (int i = 0; i < 6; i++) {
        int u = tid + i * 256;                    // < 1536
        int row = u / 24, c8 = u - row * 24;
        *(uint4*)&Ws[row * 200 + c8 * 8] = *(const uint4*)&W[(size_t)(n0 + row) * 192 + c8 * 8];
    }
    __syncthreads();

    const int warp = tid >> 5, lane = tid & 31;
    const int wm = (warp >> 1) * 32, wn = (warp & 1) * 32;
    unsigned baseA0 = smem_u32(As) + ((wm + (lane & 15)) * 200 + (lane >> 4) * 8) * 2;
    unsigned baseA1 = baseA0 + 16 * 200 * 2;
    unsigned baseB0 = smem_u32(Ws) +
        ((wn + ((lane >> 4) & 1) * 8 + (lane & 7)) * 200 + ((lane >> 3) & 1) * 8) * 2;
    unsigned baseB1 = baseB0 + 16 * 200 * 2;

    float acc[2][4][4];
    #pragma unroll
    for (int a = 0; a < 2; a++)
        #pragma unroll
        for (int b = 0; b < 4; b++)
            #pragma unroll
            for (int c = 0; c < 4; c++) acc[a][b][c] = 0.f;

    for (int ks = 0; ks < 12; ks++) {
        unsigned a0[4], a1[4], b0[4], b1[4];
        ldsm_x4(a0, baseA0 + ks * 32);
        ldsm_x4(a1, baseA1 + ks * 32);
        ldsm_x4(b0, baseB0 + ks * 32);
        ldsm_x4(b1, baseB1 + ks * 32);
        mma16816(acc[0][0], a0, b0[0], b0[1]);
        mma16816(acc[0][1], a0, b0[2], b0[3]);
        mma16816(acc[0][2], a0, b1[0], b1[1]);
        mma16816(acc[0][3], a0, b1[2], b1[3]);
        mma16816(acc[1][0], a1, b0[0], b0[1]);
        mma16816(acc[1][1], a1, b0[2], b0[3]);
        mma16816(acc[1][2], a1, b1[0], b1[1]);
        mma16816(acc[1][3], a1, b1[2], b1[3]);
    }

    #pragma unroll
    for (int mt = 0; mt < 2; mt++)
        #pragma unroll
        for (int nt = 0; nt < 4; nt++) {
            int n = n0 + wn + nt * 8 + (lane & 3) * 2;
            int mA = m0 + wm + mt * 16 + (lane >> 2);
            int mB = mA + 8;
            float b0v = bias[n], b1v = bias[n + 1];
            if (MODE == 0) {
                int sI = n / 192, rI = n - sI * 192;
                int hI = rI >> 5, dI = rI & 31;
                {
                    int win = mA / 98, tok = mA - win * 98;
                    bf16* o = g_qkv + (((size_t)sI * 1024 + win) * 6 + hI) * 3136 + tok * 32 + dI;
                    *(__nv_bfloat162*)o = __floats2bfloat162_rn(acc[mt][nt][0] + b0v, acc[mt][nt][1] + b1v);
                }
                {
                    int win = mB / 98, tok = mB - win * 98;
                    bf16* o = g_qkv + (((size_t)sI * 1024 + win) * 6 + hI) * 3136 + tok * 32 + dI;
                    *(__nv_bfloat162*)o = __floats2bfloat162_rn(acc[mt][nt][2] + b0v, acc[mt][nt][3] + b1v);
                }
            } else if (MODE == 1) {
                int tA = row_to_token(mA), tB = row_to_token(mB);
                *(__nv_bfloat162*)&g_projout[(size_t)tA * 192 + n] =
                    __floats2bfloat162_rn(acc[mt][nt][0] + b0v, acc[mt][nt][1] + b1v);
                *(__nv_bfloat162*)&g_projout[(size_t)tB * 192 + n] =
                    __floats2bfloat162_rn(acc[mt][nt][2] + b0v, acc[mt][nt][3] + b1v);
            } else {
                #pragma unroll
                for (int half = 0; half < 2; half++) {
                    int m = half ? mB : mA;
                    float va = acc[mt][nt][half * 2 + 0] + b0v;
                    float vb = acc[mt][nt][half * 2 + 1] + b1v;
                    va = 0.5f * va * (1.f + erff(va * 0.70710678118654752f));
                    vb = 0.5f * vb * (1.f + erff(vb * 0.70710678118654752f));
                    size_t off = (size_t)m * 192 + n;
                    float2 s2 = *(const float2*)&shortcut[off];
                    *(float2*)&Out[off] = make_float2(s2.x + va, s2.y + vb);
                }
            }
        }
}

// ---------------- attention: mma flash-style, one block per (window, head) --
__global__ void __launch_bounds__(128) attn_mma(const float* __restrict__ amask) {
    __shared__ __align__(16) bf16 Qs[112 * 40];
    __shared__ __align__(16) bf16 Ks[112 * 40];
    __shared__ __align__(16) bf16 Vs[112 * 40];
    const int win = blockIdx.x / 6, head = blockIdx.x - win * 6;
    const int tid = threadIdx.x, warp = tid >> 5, lane = tid & 31;
    const size_t base = ((size_t)win * 6 + head) * 3136;
    const uint4* qg = (const uint4*)(g_qkv + base);
    const uint4* kg = (const uint4*)(g_qkv + (size_t)NROWS * CDIM + base);
    const uint4* vg = (const uint4*)(g_qkv + (size_t)2 * NROWS * CDIM + base);
    for (int u = tid; u < 392; u += 128) {              // 98 rows * 4 uint4
        int row = u >> 2, c8 = u & 3;
        ((uint4*)Qs)[row * 5 + c8] = qg[u];
        ((uint4*)Ks)[row * 5 + c8] = kg[u];
        ((uint4*)Vs)[row * 5 + c8] = vg[u];
    }
    if (tid < 70) {                                     // zero V pad rows 98..111
        int row = 98 + tid / 5, c = tid - (tid / 5) * 5;
        ((uint4*)Vs)[row * 5 + c] = make_uint4(0, 0, 0, 0);
    }
    __syncthreads();

    const float* mrow = amask + (size_t)(win & 255) * 9604;
    const float* brow = g_bias6 + head * 9604;
    const unsigned sQ = smem_u32(Qs), sK = smem_u32(Ks), sV = smem_u32(Vs);
    const unsigned qoff = ((lane & 15) * 40 + (lane >> 4) * 8) * 2;
    const unsigned koff = ((((lane >> 4) & 1) * 8 + (lane & 7)) * 40 + ((lane >> 3) & 1) * 8) * 2;
    const unsigned voff = ((((lane >> 3) & 1) * 8 + (lane & 7)) * 40 + ((lane >> 4) & 1) * 8) * 2;

    for (int t = warp; t < 7; t += 4) {
        const int q0 = t * 16;
        float sacc[14][4];
        #pragma unroll
        for (int i = 0; i < 14; i++)
            #pragma unroll
            for (int j = 0; j < 4; j++) sacc[i][j] = 0.f;

        #pragma unroll
        for (int ks = 0; ks < 2; ks++) {
            unsigned a[4];
            ldsm_x4(a, sQ + q0 * 80 + qoff + ks * 32);
            #pragma unroll
            for (int p = 0; p < 7; p++) {
                unsigned b[4];
                ldsm_x4(b, sK + p * 16 * 80 + koff + ks * 32);
                mma16816(sacc[2 * p],     a, b[0], b[1]);
                mma16816(sacc[2 * p + 1], a, b[2], b[3]);
            }
        }

        const int rA = q0 + (lane >> 2), rB = rA + 8;
        const bool okA = rA < 98, okB = rB < 98;
        float mxA = -1e30f, mxB = -1e30f;
        #pragma unroll
        for (int nt = 0; nt < 14; nt++)
            #pragma unroll
            for (int e = 0; e < 2; e++) {
                int j = nt * 8 + (lane & 3) * 2 + e;
                float va = sacc[nt][e] * SCALE;
                float vb = sacc[nt][2 + e] * SCALE;
                if (j < 98) {
                    int o = j;
                    if (okA) va += brow[rA * 98 + o] + mrow[rA * 98 + o];
                    if (okB) vb += brow[rB * 98 + o] + mrow[rB * 98 + o];
                } else { va = -1e30f; vb = -1e30f; }
                sacc[nt][e] = va; sacc[nt][2 + e] = vb;
                mxA = fmaxf(mxA, va); mxB = fmaxf(mxB, vb);
            }
        mxA = fmaxf(mxA, __shfl_xor_sync(0xffffffffu, mxA, 1));
        mxA = fmaxf(mxA, __shfl_xor_sync(0xffffffffu, mxA, 2));
        mxB = fmaxf(mxB, __shfl_xor_sync(0xffffffffu, mxB, 1));
        mxB = fmaxf(mxB, __shfl_xor_sync(0xffffffffu, mxB, 2));
        float sA = 0.f, sB = 0.f;
        #pragma unroll
        for (int nt = 0; nt < 14; nt++)
            #pragma unroll
            for (int e = 0; e < 2; e++) {
                float pa = __expf(sacc[nt][e] - mxA);
                float pb = __expf(sacc[nt][2 + e] - mxB);
                sacc[nt][e] = pa; sacc[nt][2 + e] = pb;
                sA += pa; sB += pb;
            }
        sA += __shfl_xor_sync(0xffffffffu, sA, 1);
        sA += __shfl_xor_sync(0xffffffffu, sA, 2);
        sB += __shfl_xor_sync(0xffffffffu, sB, 1);
        sB += __shfl_xor_sync(0xffffffffu, sB, 2);
        const float invA = 1.f / sA, invB = 1.f / sB;

        float oacc[4][4];
        #pragma unroll
        for (int i = 0; i < 4; i++)
            #pragma unroll
            for (int j = 0; j < 4; j++) oacc[i][j] = 0.f;

        #pragma unroll
        for (int kt = 0; kt < 7; kt++) {
            unsigned pa[4];
            pa[0] = pack2(sacc[2 * kt][0],     sacc[2 * kt][1]);
            pa[1] = pack2(sacc[2 * kt][2],     sacc[2 * kt][3]);
            pa[2] = pack2(sacc[2 * kt + 1][0], sacc[2 * kt + 1][1]);
            pa[3] = pack2(sacc[2 * kt + 1][2], sacc[2 * kt + 1][3]);
            #pragma unroll
            for (int dp = 0; dp < 2; dp++) {
                unsigned b[4];
                ldsm_x4_t(b, sV + kt * 16 * 80 + voff + dp * 32);
                mma16816(oacc[2 * dp],     pa, b[0], b[1]);
                mma16816(oacc[2 * dp + 1], pa, b[2], b[3]);
            }
        }

        #pragma unroll
        for (int dt = 0; dt < 4; dt++) {
            int d = head * 32 + dt * 8 + (lane & 3) * 2;
            if (okA)
                *(__nv_bfloat162*)&g_attnout[(size_t)(win * 98 + rA) * 192 + d] =
                    __floats2bfloat162_rn(oacc[dt][0] * invA, oacc[dt][1] * invA);
            if (okB)
                *(__nv_bfloat162*)&g_attnout[(size_t)(win * 98 + rB) * 192 + d] =
                    __floats2bfloat162_rn(oacc[dt][2] * invB, oacc[dt][3] * invB);
        }
    }
}

// ---------------- launch ----------------------------------------------------
extern "C" void kernel_launch(void* const* d_in, const int* in_sizes, int n_in,
                              void* d_out, int out_size) {
    const float* x     = (const float*)d_in[0];
    const float* amask = (const float*)d_in[1];
    const float* n1g   = (const float*)d_in[2];
    const float* n1b   = (const float*)d_in[3];
    const float* qkvw  = (const float*)d_in[4];
    const float* qkvb  = (const float*)d_in[5];
    const float* relb  = (const float*)d_in[6];
    const float* projw = (const float*)d_in[7];
    const float* projb = (const float*)d_in[8];
    const float* fc1w  = (const float*)d_in[9];
    const float* fc1b  = (const float*)d_in[10];
    float* out = (float*)d_out;
    (void)in_sizes; (void)n_in; (void)out_size;

    const int SMEM = (128 + 64) * 200 * 2;   // 76800 B
    cudaFuncSetAttribute(gemm_mma<0>, cudaFuncAttributeMaxDynamicSharedMemorySize, SMEM);
    cudaFuncSetAttribute(gemm_mma<1>, cudaFuncAttributeMaxDynamicSharedMemorySize, SMEM);
    cudaFuncSetAttribute(gemm_mma<2>, cudaFuncAttributeMaxDynamicSharedMemorySize, SMEM);

    convert_w_k<<<720, 256>>>(qkvw, projw, fc1w);
    bias_expand_k<<<38, 256>>>(relb);
    ln_gather_k<<<12544, 256>>>(x, n1g, n1b);
    gemm_mma<0><<<dim3(9, 784), 256, SMEM>>>(qkvb, nullptr, nullptr);
    attn_mma<<<6144, 128>>>(amask);
    gemm_mma<1><<<dim3(3, 784), 256, SMEM>>>(projb, nullptr, nullptr);
    gemm_mma<2><<<dim3(3, 784), 256, SMEM>>>(fc1b, x, out);
}

// round 7
// speedup vs baseline: 6.2754x; 1.2232x over previous
#include <cuda_runtime.h>
#include <cuda_bf16.h>
#include <cuda_pipeline.h>
#include <math.h>

#define NROWS 100352   // B*D*H*W tokens == total window rows (1024 windows * 98)
#define CDIM  192
#define SCALE 0.17677669529663687f

typedef __nv_bfloat16 bf16;

// ---------------- scratch (device globals) ----------------------------------
__device__ bf16 g_xw[(size_t)NROWS * CDIM];        // LN'd+rolled+partitioned (window-row major)
__device__ bf16 g_qkv[(size_t)3 * NROWS * CDIM];   // [3][win][head][98][32]
__device__ bf16 g_attnout[(size_t)NROWS * CDIM];   // window-row major, col = head*32+d
__device__ bf16 g_projout[(size_t)NROWS * CDIM];   // token major
__device__ bf16 g_wq[576 * 192];
__device__ bf16 g_wp[192 * 192];
__device__ bf16 g_wf[192 * 192];
__device__ bf16 g_mb[(size_t)256 * 6 * 98 * 98];   // combined rel_bias + shift mask

// ---------------- helpers ---------------------------------------------------
__device__ __forceinline__ int row_to_token(int row) {
    int win = row / 98;
    int tok = row - win * 98;
    int b = win >> 8, wib = win & 255;
    int wd = wib >> 6, wh = (wib >> 3) & 7, wwi = wib & 7;
    int md = tok / 49; int r2 = tok - md * 49; int mh = r2 / 7; int mw = r2 - mh * 7;
    int d = (wd * 2 + md + 1) & 7;
    int h = wh * 7 + mh + 3; if (h >= 56) h -= 56;
    int w = wwi * 7 + mw + 3; if (w >= 56) w -= 56;
    return ((b * 8 + d) * 56 + h) * 56 + w;
}

__device__ __forceinline__ unsigned smem_u32(const void* p) {
    return (unsigned)__cvta_generic_to_shared(p);
}
__device__ __forceinline__ void ldsm_x4(unsigned r[4], unsigned addr) {
    asm volatile("ldmatrix.sync.aligned.m8n8.x4.shared.b16 {%0,%1,%2,%3}, [%4];"
                 : "=r"(r[0]), "=r"(r[1]), "=r"(r[2]), "=r"(r[3]) : "r"(addr));
}
__device__ __forceinline__ void ldsm_x4_t(unsigned r[4], unsigned addr) {
    asm volatile("ldmatrix.sync.aligned.m8n8.x4.trans.shared.b16 {%0,%1,%2,%3}, [%4];"
                 : "=r"(r[0]), "=r"(r[1]), "=r"(r[2]), "=r"(r[3]) : "r"(addr));
}
__device__ __forceinline__ void mma16816(float c[4], const unsigned a[4], unsigned b0, unsigned b1) {
    asm volatile("mma.sync.aligned.m16n8k16.row.col.f32.bf16.bf16.f32 "
                 "{%0,%1,%2,%3},{%4,%5,%6,%7},{%8,%9},{%0,%1,%2,%3};"
                 : "+f"(c[0]), "+f"(c[1]), "+f"(c[2]), "+f"(c[3])
                 : "r"(a[0]), "r"(a[1]), "r"(a[2]), "r"(a[3]), "r"(b0), "r"(b1));
}
__device__ __forceinline__ unsigned pack2(float lo, float hi) {
    __nv_bfloat162 h = __floats2bfloat162_rn(lo, hi);
    return *reinterpret_cast<unsigned*>(&h);
}

// ---------------- tiny prep kernels -----------------------------------------
__global__ void convert_w_k(const float* __restrict__ qw, const float* __restrict__ pw,
                            const float* __restrict__ fw) {
    int i = blockIdx.x * 256 + threadIdx.x;          // 184320 total
    if (i < 110592)       g_wq[i] = __float2bfloat16(qw[i]);
    else if (i < 147456)  g_wp[i - 110592] = __float2bfloat16(pw[i - 110592]);
    else                  g_wf[i - 147456] = __float2bfloat16(fw[i - 147456]);
}

// combined mask+bias table: g_mb[w][h][q][j] = rel_bias[REL_IDX[q][j]][h] + amask[w][q][j]
__global__ void mb_combine_k(const float* __restrict__ amask, const float* __restrict__ relb) {
    int idx = blockIdx.x * 256 + threadIdx.x;        // 256*9604 total
    if (idx >= 256 * 9604) return;
    int w = idx / 9604, i = idx - w * 9604;
    int q = i / 98, j = i - q * 98;
    int nd = q / 49, r2 = q % 49, nh = r2 / 7, nw = r2 % 7;
    int md = j / 49, m2 = j % 49, mh = m2 / 7, mw = m2 % 7;
    int ridx = (nd - md + 1) * 169 + (nh - mh + 6) * 13 + (nw - mw + 6);
    float m = amask[(size_t)w * 9604 + i];
    #pragma unroll
    for (int h = 0; h < 6; h++)
        g_mb[((size_t)w * 6 + h) * 9604 + i] = __float2bfloat16(relb[ridx * 6 + h] + m);
}

// ---------------- LayerNorm + roll + window partition ------------------------
__global__ void __launch_bounds__(256) ln_gather_k(const float* __restrict__ x,
        const float* __restrict__ gg, const float* __restrict__ bb) {
    int row = blockIdx.x * 8 + (threadIdx.x >> 5);
    int lane = threadIdx.x & 31;
    int t = row_to_token(row);
    const float* xp = x + (size_t)t * CDIM;
    float v[6]; float s = 0.f;
    #pragma unroll
    for (int j = 0; j < 6; j++) { v[j] = xp[lane + 32 * j]; s += v[j]; }
    #pragma unroll
    for (int o = 16; o > 0; o >>= 1) s += __shfl_xor_sync(0xffffffffu, s, o);
    float mu = s * (1.f / 192.f);
    float var = 0.f;
    #pragma unroll
    for (int j = 0; j < 6; j++) { float dd = v[j] - mu; var += dd * dd; }
    #pragma unroll
    for (int o = 16; o > 0; o >>= 1) var += __shfl_xor_sync(0xffffffffu, var, o);
    float r = rsqrtf(var * (1.f / 192.f) + 1e-5f);
    bf16* op = g_xw + (size_t)row * CDIM;
    #pragma unroll
    for (int j = 0; j < 6; j++) {
        int c = lane + 32 * j;
        op[c] = __float2bfloat16((v[j] - mu) * r * gg[c] + bb[c]);
    }
}

// ---------------- bf16 tensor-core GEMM: C(MxN) = A(Mx192) @ W(Nx192)^T ------
// CTA 128x64, 8 warps (32x32 each). Swizzled smem (stride 192, XOR bank swizzle),
// cp.async two-half K pipeline. MODE 0: QKV scatter. MODE 1: proj token scatter.
// MODE 2: fc1 -> out = shortcut + gelu(acc+bias).
template<int MODE>
__global__ void __launch_bounds__(256) gemm_mma(const float* __restrict__ bias,
        const float* __restrict__ shortcut, float* __restrict__ Out) {
    extern __shared__ __align__(16) char sm[];       // As: 128x384B, Ws at +49152: 64x384B
    const bf16* A = (MODE == 0) ? g_xw : (MODE == 1) ? g_attnout : g_projout;
    const bf16* W = (MODE == 0) ? g_wq : (MODE == 1) ? g_wp : g_wf;
    const int tid = threadIdx.x;
    const int m0 = blockIdx.y * 128, n0 = blockIdx.x * 64;

    // ---- async loads, two K-halves (groups of 8 bf16 = 16B) ----
    #pragma unroll
    for (int half = 0; half < 2; half++) {
        #pragma unroll
        for (int i = 0; i < 6; i++) {
            int u = tid + i * 256;                   // < 1536 = 128 rows * 12 groups
            int row = u / 12, g = u - row * 12 + half * 12;
            __pipeline_memcpy_async(sm + row * 384 + ((g ^ (row & 7)) << 4),
                                    &A[(size_t)(m0 + row) * 192 + g * 8], 16);
        }
        #pragma unroll
        for (int i = 0; i < 3; i++) {
            int u = tid + i * 256;                   // < 768 = 64 rows * 12 groups
            int row = u / 12, g = u - row * 12 + half * 12;
            __pipeline_memcpy_async(sm + 49152 + row * 384 + ((g ^ (row & 7)) << 4),
                                    &W[(size_t)(n0 + row) * 192 + g * 8], 16);
        }
        __pipeline_commit();
    }

    const int warp = tid >> 5, lane = tid & 31;
    const int wm = (warp >> 1) * 32, wn = (warp & 1) * 32;
    const unsigned base_s = smem_u32(sm);
    const unsigned xo = lane & 7;
    const unsigned hA = lane >> 4, hB = (lane >> 3) & 1;
    const unsigned bA0 = base_s + (wm + (lane & 15)) * 384;
    const unsigned bA1 = bA0 + 16 * 384;
    const unsigned bB0 = base_s + 49152 + (wn + ((lane >> 4) & 1) * 8 + (lane & 7)) * 384;
    const unsigned bB1 = bB0 + 16 * 384;

    float acc[2][4][4];
    #pragma unroll
    for (int a = 0; a < 2; a++)
        #pragma unroll
        for (int b = 0; b < 4; b++)
            #pragma unroll
            for (int c = 0; c < 4; c++) acc[a][b][c] = 0.f;

    __pipeline_wait_prior(1);
    __syncthreads();
    #pragma unroll
    for (int ks = 0; ks < 6; ks++) {
        unsigned a0[4], a1[4], b0[4], b1[4];
        unsigned offA = ((2 * ks + hA) ^ xo) << 4, offB = ((2 * ks + hB) ^ xo) << 4;
        ldsm_x4(a0, bA0 + offA); ldsm_x4(a1, bA1 + offA);
        ldsm_x4(b0, bB0 + offB); ldsm_x4(b1, bB1 + offB);
        mma16816(acc[0][0], a0, b0[0], b0[1]); mma16816(acc[0][1], a0, b0[2], b0[3]);
        mma16816(acc[0][2], a0, b1[0], b1[1]); mma16816(acc[0][3], a0, b1[2], b1[3]);
        mma16816(acc[1][0], a1, b0[0], b0[1]); mma16816(acc[1][1], a1, b0[2], b0[3]);
        mma16816(acc[1][2], a1, b1[0], b1[1]); mma16816(acc[1][3], a1, b1[2], b1[3]);
    }
    __pipeline_wait_prior(0);
    __syncthreads();
    #pragma unroll
    for (int ks = 6; ks < 12; ks++) {
        unsigned a0[4], a1[4], b0[4], b1[4];
        unsigned offA = ((2 * ks + hA) ^ xo) << 4, offB = ((2 * ks + hB) ^ xo) << 4;
        ldsm_x4(a0, bA0 + offA); ldsm_x4(a1, bA1 + offA);
        ldsm_x4(b0, bB0 + offB); ldsm_x4(b1, bB1 + offB);
        mma16816(acc[0][0], a0, b0[0], b0[1]); mma16816(acc[0][1], a0, b0[2], b0[3]);
        mma16816(acc[0][2], a0, b1[0], b1[1]); mma16816(acc[0][3], a0, b1[2], b1[3]);
        mma16816(acc[1][0], a1, b0[0], b0[1]); mma16816(acc[1][1], a1, b0[2], b0[3]);
        mma16816(acc[1][2], a1, b1[0], b1[1]); mma16816(acc[1][3], a1, b1[2], b1[3]);
    }

    #pragma unroll
    for (int mt = 0; mt < 2; mt++)
        #pragma unroll
        for (int nt = 0; nt < 4; nt++) {
            int n = n0 + wn + nt * 8 + (lane & 3) * 2;
            int mA = m0 + wm + mt * 16 + (lane >> 2);
            int mB = mA + 8;
            float b0v = bias[n], b1v = bias[n + 1];
            if (MODE == 0) {
                int sI = n / 192, rI = n - sI * 192;
                int hI = rI >> 5, dI = rI & 31;
                {
                    int win = mA / 98, tok = mA - win * 98;
                    bf16* o = g_qkv + (((size_t)sI * 1024 + win) * 6 + hI) * 3136 + tok * 32 + dI;
                    *(__nv_bfloat162*)o = __floats2bfloat162_rn(acc[mt][nt][0] + b0v, acc[mt][nt][1] + b1v);
                }
                {
                    int win = mB / 98, tok = mB - win * 98;
                    bf16* o = g_qkv + (((size_t)sI * 1024 + win) * 6 + hI) * 3136 + tok * 32 + dI;
                    *(__nv_bfloat162*)o = __floats2bfloat162_rn(acc[mt][nt][2] + b0v, acc[mt][nt][3] + b1v);
                }
            } else if (MODE == 1) {
                int tA = row_to_token(mA), tB = row_to_token(mB);
                *(__nv_bfloat162*)&g_projout[(size_t)tA * 192 + n] =
                    __floats2bfloat162_rn(acc[mt][nt][0] + b0v, acc[mt][nt][1] + b1v);
                *(__nv_bfloat162*)&g_projout[(size_t)tB * 192 + n] =
                    __floats2bfloat162_rn(acc[mt][nt][2] + b0v, acc[mt][nt][3] + b1v);
            } else {
                #pragma unroll
                for (int half = 0; half < 2; half++) {
                    int m = half ? mB : mA;
                    float va = acc[mt][nt][half * 2 + 0] + b0v;
                    float vb = acc[mt][nt][half * 2 + 1] + b1v;
                    va = 0.5f * va * (1.f + erff(va * 0.70710678118654752f));
                    vb = 0.5f * vb * (1.f + erff(vb * 0.70710678118654752f));
                    size_t off = (size_t)m * 192 + n;
                    float2 s2 = *(const float2*)&shortcut[off];
                    *(float2*)&Out[off] = make_float2(s2.x + va, s2.y + vb);
                }
            }
        }
}

// ---------------- attention: mma flash-style, one block per (window, head) --
__global__ void __launch_bounds__(128) attn_mma() {
    __shared__ __align__(16) bf16 Qs[112 * 40];
    __shared__ __align__(16) bf16 Ks[112 * 40];
    __shared__ __align__(16) bf16 Vs[112 * 40];
    const int win = blockIdx.x / 6, head = blockIdx.x - win * 6;
    const int tid = threadIdx.x, warp = tid >> 5, lane = tid & 31;
    const size_t base = ((size_t)win * 6 + head) * 3136;
    const uint4* qg = (const uint4*)(g_qkv + base);
    const uint4* kg = (const uint4*)(g_qkv + (size_t)NROWS * CDIM + base);
    const uint4* vg = (const uint4*)(g_qkv + (size_t)2 * NROWS * CDIM + base);
    for (int u = tid; u < 392; u += 128) {              // 98 rows * 4 uint4
        int row = u >> 2, c8 = u & 3;
        ((uint4*)Qs)[row * 5 + c8] = qg[u];
        ((uint4*)Ks)[row * 5 + c8] = kg[u];
        ((uint4*)Vs)[row * 5 + c8] = vg[u];
    }
    if (tid < 70) {                                     // zero V pad rows 98..111
        int row = 98 + tid / 5, c = tid - (tid / 5) * 5;
        ((uint4*)Vs)[row * 5 + c] = make_uint4(0, 0, 0, 0);
    }
    __syncthreads();

    const bf16* mbrow = g_mb + ((size_t)(win & 255) * 6 + head) * 9604;
    const unsigned sQ = smem_u32(Qs), sK = smem_u32(Ks), sV = smem_u32(Vs);
    const unsigned qoff = ((lane & 15) * 40 + (lane >> 4) * 8) * 2;
    const unsigned koff = ((((lane >> 4) & 1) * 8 + (lane & 7)) * 40 + ((lane >> 3) & 1) * 8) * 2;
    const unsigned voff = ((((lane >> 3) & 1) * 8 + (lane & 7)) * 40 + ((lane >> 4) & 1) * 8) * 2;

    for (int t = warp; t < 7; t += 4) {
        const int q0 = t * 16;
        float sacc[14][4];
        #pragma unroll
        for (int i = 0; i < 14; i++)
            #pragma unroll
            for (int j = 0; j < 4; j++) sacc[i][j] = 0.f;

        #pragma unroll
        for (int ks = 0; ks < 2; ks++) {
            unsigned a[4];
            ldsm_x4(a, sQ + q0 * 80 + qoff + ks * 32);
            #pragma unroll
            for (int p = 0; p < 7; p++) {
                unsigned b[4];
                ldsm_x4(b, sK + p * 16 * 80 + koff + ks * 32);
                mma16816(sacc[2 * p],     a, b[0], b[1]);
                mma16816(sacc[2 * p + 1], a, b[2], b[3]);
            }
        }

        const int rA = q0 + (lane >> 2), rB = rA + 8;
        const bool okA = rA < 98, okB = rB < 98;
        float mxA = -1e30f, mxB = -1e30f;
        #pragma unroll
        for (int nt = 0; nt < 14; nt++) {
            int j0 = nt * 8 + (lane & 3) * 2;
            float va0 = sacc[nt][0] * SCALE, va1 = sacc[nt][1] * SCALE;
            float vb0 = sacc[nt][2] * SCALE, vb1 = sacc[nt][3] * SCALE;
            if (j0 < 98) {
                if (okA) {
                    __nv_bfloat162 p = *(const __nv_bfloat162*)&mbrow[rA * 98 + j0];
                    va0 += __low2float(p); va1 += __high2float(p);
                }
                if (okB) {
                    __nv_bfloat162 p = *(const __nv_bfloat162*)&mbrow[rB * 98 + j0];
                    vb0 += __low2float(p); vb1 += __high2float(p);
                }
            } else { va0 = va1 = vb0 = vb1 = -1e30f; }
            sacc[nt][0] = va0; sacc[nt][1] = va1;
            sacc[nt][2] = vb0; sacc[nt][3] = vb1;
            mxA = fmaxf(mxA, fmaxf(va0, va1));
            mxB = fmaxf(mxB, fmaxf(vb0, vb1));
        }
        mxA = fmaxf(mxA, __shfl_xor_sync(0xffffffffu, mxA, 1));
        mxA = fmaxf(mxA, __shfl_xor_sync(0xffffffffu, mxA, 2));
        mxB = fmaxf(mxB, __shfl_xor_sync(0xffffffffu, mxB, 1));
        mxB = fmaxf(mxB, __shfl_xor_sync(0xffffffffu, mxB, 2));
        float sA = 0.f, sB = 0.f;
        #pragma unroll
        for (int nt = 0; nt < 14; nt++) {
            float pa0 = __expf(sacc[nt][0] - mxA), pa1 = __expf(sacc[nt][1] - mxA);
            float pb0 = __expf(sacc[nt][2] - mxB), pb1 = __expf(sacc[nt][3] - mxB);
            sacc[nt][0] = pa0; sacc[nt][1] = pa1;
            sacc[nt][2] = pb0; sacc[nt][3] = pb1;
            sA += pa0 + pa1; sB += pb0 + pb1;
        }
        sA += __shfl_xor_sync(0xffffffffu, sA, 1);
        sA += __shfl_xor_sync(0xffffffffu, sA, 2);
        sB += __shfl_xor_sync(0xffffffffu, sB, 1);
        sB += __shfl_xor_sync(0xffffffffu, sB, 2);
        const float invA = 1.f / sA, invB = 1.f / sB;

        float oacc[4][4];
        #pragma unroll
        for (int i = 0; i < 4; i++)
            #pragma unroll
            for (int j = 0; j < 4; j++) oacc[i][j] = 0.f;

        #pragma unroll
        for (int kt = 0; kt < 7; kt++) {
            unsigned pa[4];
            pa[0] = pack2(sacc[2 * kt][0],     sacc[2 * kt][1]);
            pa[1] = pack2(sacc[2 * kt][2],     sacc[2 * kt][3]);
            pa[2] = pack2(sacc[2 * kt + 1][0], sacc[2 * kt + 1][1]);
            pa[3] = pack2(sacc[2 * kt + 1][2], sacc[2 * kt + 1][3]);
            #pragma unroll
            for (int dp = 0; dp < 2; dp++) {
                unsigned b[4];
                ldsm_x4_t(b, sV + kt * 16 * 80 + voff + dp * 32);
                mma16816(oacc[2 * dp],     pa, b[0], b[1]);
                mma16816(oacc[2 * dp + 1], pa, b[2], b[3]);
            }
        }

        #pragma unroll
        for (int dt = 0; dt < 4; dt++) {
            int d = head * 32 + dt * 8 + (lane & 3) * 2;
            if (okA)
                *(__nv_bfloat162*)&g_attnout[(size_t)(win * 98 + rA) * 192 + d] =
                    __floats2bfloat162_rn(oacc[dt][0] * invA, oacc[dt][1] * invA);
            if (okB)
                *(__nv_bfloat162*)&g_attnout[(size_t)(win * 98 + rB) * 192 + d] =
                    __floats2bfloat162_rn(oacc[dt][2] * invB, oacc[dt][3] * invB);
        }
    }
}

// ---------------- launch ----------------------------------------------------
extern "C" void kernel_launch(void* const* d_in, const int* in_sizes, int n_in,
                              void* d_out, int out_size) {
    const float* x     = (const float*)d_in[0];
    const float* amask = (const float*)d_in[1];
    const float* n1g   = (const float*)d_in[2];
    const float* n1b   = (const float*)d_in[3];
    const float* qkvw  = (const float*)d_in[4];
    const float* qkvb  = (const float*)d_in[5];
    const float* relb  = (const float*)d_in[6];
    const float* projw = (const float*)d_in[7];
    const float* projb = (const float*)d_in[8];
    const float* fc1w  = (const float*)d_in[9];
    const float* fc1b  = (const float*)d_in[10];
    float* out = (float*)d_out;
    (void)in_sizes; (void)n_in; (void)out_size;

    const int SMEM = (128 + 64) * 192 * 2;   // 73728 B (swizzled, no padding)
    cudaFuncSetAttribute(gemm_mma<0>, cudaFuncAttributeMaxDynamicSharedMemorySize, SMEM);
    cudaFuncSetAttribute(gemm_mma<1>, cudaFuncAttributeMaxDynamicSharedMemorySize, SMEM);
    cudaFuncSetAttribute(gemm_mma<2>, cudaFuncAttributeMaxDynamicSharedMemorySize, SMEM);

    convert_w_k<<<720, 256>>>(qkvw, projw, fc1w);
    mb_combine_k<<<9604, 256>>>(amask, relb);
    ln_gather_k<<<12544, 256>>>(x, n1g, n1b);
    gemm_mma<0><<<dim3(9, 784), 256, SMEM>>>(qkvb, nullptr, nullptr);
    attn_mma<<<6144, 128>>>();
    gemm_mma<1><<<dim3(3, 784), 256, SMEM>>>(projb, nullptr, nullptr);
    gemm_mma<2><<<dim3(3, 784), 256, SMEM>>>(fc1b, x, out);
}